// round 2
// baseline (speedup 1.0000x reference)
#include <cuda_runtime.h>
#include <cuda_bf16.h>
#include <math.h>

#define BATCH 4
#define SEQ   512
#define DM    1024
#define NH    16
#define NL    8
#define VOCAB 32000
#define HDIM  64
#define DFF   4096
#define MROWS (BATCH*SEQ)   // 2048

// ---------------- scratch (static device globals; no allocation) ----------------
__device__ float g_x [MROWS*DM];
__device__ float g_t0[MROWS*DM];
__device__ float g_t1[MROWS*DM];
__device__ float g_t2[MROWS*DM];
__device__ float g_t3[MROWS*DM];
__device__ float g_f1[MROWS*DFF];

// ---------------- embedding + positional (pe indexed by BATCH, per reference) ----
__global__ void embed_kernel(const int* __restrict__ tokens,
                             const float* __restrict__ emb,
                             const float* __restrict__ pe,
                             float* __restrict__ x)
{
    int idx = blockIdx.x * blockDim.x + threadIdx.x;
    if (idx >= MROWS * DM) return;
    int d  = idx % DM;
    int nt = idx / DM;          // n*SEQ + t
    int n  = nt / SEQ;
    int tok = tokens[nt];
    x[idx] = emb[(size_t)tok * DM + d] + pe[(size_t)n * DM + d];
}

// ---------------- SGEMM: C(MxN) = A(MxK) @ B(KxN) + bias, optional ReLU ---------
// 128x128 block tile, BK=8, 256 threads, 8x8 per thread (two 4x4 quadrants).
#define BM 128
#define BN 128
#define BK 8
#define ASTR 132   // padded stride for As to kill store bank conflicts

template<bool RELU>
__global__ void __launch_bounds__(256)
sgemm_bias(const float* __restrict__ A, const float* __restrict__ B,
           const float* __restrict__ bias, float* __restrict__ C,
           int M, int Nn, int K)
{
    __shared__ float As[BK * ASTR];
    __shared__ float Bs[BK * BN];

    int tid = threadIdx.x;
    const float* Ab = A + (size_t)blockIdx.x * BM * K;
    const float* Bb = B + (size_t)blockIdx.y * BN;
    float*       Cb = C + (size_t)blockIdx.x * BM * Nn + (size_t)blockIdx.y * BN;

    int arow = tid >> 1;           // 0..127
    int acol = (tid & 1) * 4;      // 0 or 4
    int brow = tid >> 5;           // 0..7
    int bcol = (tid & 31) * 4;     // 0..124

    int tx = tid & 15;             // 0..15
    int ty = tid >> 4;             // 0..15

    float acc[8][8];
#pragma unroll
    for (int i = 0; i < 8; i++)
#pragma unroll
        for (int j = 0; j < 8; j++) acc[i][j] = 0.f;

    for (int k0 = 0; k0 < K; k0 += BK) {
        float4 a4 = *(const float4*)(Ab + (size_t)arow * K + k0 + acol);
        As[(acol + 0) * ASTR + arow] = a4.x;
        As[(acol + 1) * ASTR + arow] = a4.y;
        As[(acol + 2) * ASTR + arow] = a4.z;
        As[(acol + 3) * ASTR + arow] = a4.w;
        float4 b4 = *(const float4*)(Bb + (size_t)(k0 + brow) * Nn + bcol);
        *(float4*)(Bs + brow * BN + bcol) = b4;
        __syncthreads();

#pragma unroll
        for (int k = 0; k < BK; k++) {
            float4 a0 = *(const float4*)(As + k * ASTR + ty * 4);
            float4 a1 = *(const float4*)(As + k * ASTR + 64 + ty * 4);
            float4 b0 = *(const float4*)(Bs + k * BN + tx * 4);
            float4 b1 = *(const float4*)(Bs + k * BN + 64 + tx * 4);
            float ar[8] = {a0.x, a0.y, a0.z, a0.w, a1.x, a1.y, a1.z, a1.w};
            float br[8] = {b0.x, b0.y, b0.z, b0.w, b1.x, b1.y, b1.z, b1.w};
#pragma unroll
            for (int i = 0; i < 8; i++)
#pragma unroll
                for (int j = 0; j < 8; j++)
                    acc[i][j] += ar[i] * br[j];
        }
        __syncthreads();
    }

    // epilogue
#pragma unroll
    for (int ih = 0; ih < 2; ih++) {
#pragma unroll
        for (int ii = 0; ii < 4; ii++) {
            int row = ih * 64 + ty * 4 + ii;
#pragma unroll
            for (int jh = 0; jh < 2; jh++) {
                int col = jh * 64 + tx * 4;
                const float* bp = bias + (size_t)blockIdx.y * BN + col;
                float4 r;
                r.x = acc[ih * 4 + ii][jh * 4 + 0] + bp[0];
                r.y = acc[ih * 4 + ii][jh * 4 + 1] + bp[1];
                r.z = acc[ih * 4 + ii][jh * 4 + 2] + bp[2];
                r.w = acc[ih * 4 + ii][jh * 4 + 3] + bp[3];
                if (RELU) {
                    r.x = fmaxf(r.x, 0.f); r.y = fmaxf(r.y, 0.f);
                    r.z = fmaxf(r.z, 0.f); r.w = fmaxf(r.w, 0.f);
                }
                *(float4*)(Cb + (size_t)row * Nn + col) = r;
            }
        }
    }
}

// ---------------- causal attention (flash-style, fp32) --------------------------
// grid: (SEQ/128, NH, BATCH), 128 threads. Each thread owns one query row.
// smem: qs[128][65] | ks[64][65] | vs[64][65] | scs[128][65]
#define ATTN_SMEM ((128*65 + 64*65 + 64*65 + 128*65) * 4)

__global__ void __launch_bounds__(128)
attn_kernel(const float* __restrict__ q, const float* __restrict__ k,
            const float* __restrict__ v, float* __restrict__ o)
{
    extern __shared__ float sm[];
    float* qs  = sm;                  // 128*65
    float* ks  = qs + 128 * 65;       // 64*65
    float* vs  = ks + 64 * 65;        // 64*65
    float* scs = vs + 64 * 65;        // 128*65

    int n  = blockIdx.z;
    int h  = blockIdx.y;
    int qt = blockIdx.x;
    int tid = threadIdx.x;
    int r = qt * 128 + tid;           // global query row (< SEQ)

    // load q tile (128 rows x 64 cols), coalesced
    for (int i = tid; i < 128 * 16; i += 128) {
        int row = i >> 4, c4 = (i & 15) * 4;
        float4 t = *(const float4*)(q + ((size_t)(n * SEQ + qt * 128 + row)) * DM + h * HDIM + c4);
        qs[row * 65 + c4 + 0] = t.x; qs[row * 65 + c4 + 1] = t.y;
        qs[row * 65 + c4 + 2] = t.z; qs[row * 65 + c4 + 3] = t.w;
    }
    __syncthreads();

    float qreg[64];
#pragma unroll
    for (int d = 0; d < 64; d++) qreg[d] = qs[tid * 65 + d] * 0.125f;  // 1/sqrt(64)

    float m = -1e30f, l = 0.f;
    float acc[64];
#pragma unroll
    for (int d = 0; d < 64; d++) acc[d] = 0.f;

    int smax = qt * 128 + 127;
    for (int s0 = 0; s0 <= smax; s0 += 64) {
        // load K,V tiles (64 x 64)
        for (int i = tid; i < 64 * 16; i += 128) {
            int row = i >> 4, c4 = (i & 15) * 4;
            size_t base = ((size_t)(n * SEQ + s0 + row)) * DM + h * HDIM + c4;
            float4 kk = *(const float4*)(k + base);
            ks[row * 65 + c4 + 0] = kk.x; ks[row * 65 + c4 + 1] = kk.y;
            ks[row * 65 + c4 + 2] = kk.z; ks[row * 65 + c4 + 3] = kk.w;
            float4 vv = *(const float4*)(v + base);
            vs[row * 65 + c4 + 0] = vv.x; vs[row * 65 + c4 + 1] = vv.y;
            vs[row * 65 + c4 + 2] = vv.z; vs[row * 65 + c4 + 3] = vv.w;
        }
        __syncthreads();

        // scores for this tile (per-thread private row of scs)
        float tmax = -1e30f;
        for (int s = 0; s < 64; s++) {
            float sc;
            if (s0 + s > r) {
                sc = -1e30f;
            } else {
                sc = 0.f;
#pragma unroll
                for (int d = 0; d < 64; d++) sc += qreg[d] * ks[s * 65 + d];
            }
            scs[tid * 65 + s] = sc;
            tmax = fmaxf(tmax, sc);
        }

        float nm = fmaxf(m, tmax);
        float cf = __expf(m - nm);
        l *= cf;
#pragma unroll
        for (int d = 0; d < 64; d++) acc[d] *= cf;

        for (int s = 0; s < 64; s++) {
            float p = __expf(scs[tid * 65 + s] - nm);
            l += p;
#pragma unroll
            for (int d = 0; d < 64; d++) acc[d] += p * vs[s * 65 + d];
        }
        m = nm;
        __syncthreads();
    }

    float inv = 1.f / l;
    float* op = o + ((size_t)(n * SEQ + r)) * DM + h * HDIM;
#pragma unroll
    for (int d0 = 0; d0 < 64; d0 += 4) {
        float4 t;
        t.x = acc[d0 + 0] * inv; t.y = acc[d0 + 1] * inv;
        t.z = acc[d0 + 2] * inv; t.w = acc[d0 + 3] * inv;
        *(float4*)(op + d0) = t;
    }
}

// ---------------- residual + LayerNorm: x += LN(o)*g + b ------------------------
__global__ void __launch_bounds__(256)
ln_residual(float* __restrict__ x, const float* __restrict__ o,
            const float* __restrict__ g, const float* __restrict__ b)
{
    __shared__ float red[256];
    __shared__ float s_mean, s_rstd;
    int row = blockIdx.x;
    int tid = threadIdx.x;
    const float* orow = o + (size_t)row * DM;
    float*       xrow = x + (size_t)row * DM;

    float s = 0.f;
    for (int d = tid; d < DM; d += 256) s += orow[d];
    red[tid] = s; __syncthreads();
    for (int off = 128; off > 0; off >>= 1) {
        if (tid < off) red[tid] += red[tid + off];
        __syncthreads();
    }
    if (tid == 0) s_mean = red[0] * (1.f / DM);
    __syncthreads();
    float mean = s_mean;

    float vv = 0.f;
    for (int d = tid; d < DM; d += 256) { float t = orow[d] - mean; vv += t * t; }
    red[tid] = vv; __syncthreads();
    for (int off = 128; off > 0; off >>= 1) {
        if (tid < off) red[tid] += red[tid + off];
        __syncthreads();
    }
    if (tid == 0) s_rstd = rsqrtf(red[0] * (1.f / DM) + 1e-5f);
    __syncthreads();
    float rstd = s_rstd;

    for (int d = tid; d < DM; d += 256)
        xrow[d] += (orow[d] - mean) * rstd * g[d] + b[d];
}

// ---------------- launch --------------------------------------------------------
extern "C" void kernel_launch(void* const* d_in, const int* in_sizes, int n_in,
                              void* d_out, int out_size)
{
    const int*   tokens = (const int*)  d_in[0];
    const float* emb    = (const float*)d_in[1];
    const float* pe     = (const float*)d_in[2];
    const float* Wq     = (const float*)d_in[3];
    const float* bq     = (const float*)d_in[4];
    const float* Wk     = (const float*)d_in[5];
    const float* bk     = (const float*)d_in[6];
    const float* Wv     = (const float*)d_in[7];
    const float* bv     = (const float*)d_in[8];
    const float* Wo     = (const float*)d_in[9];
    const float* bo     = (const float*)d_in[10];
    const float* g1     = (const float*)d_in[11];
    const float* be1    = (const float*)d_in[12];
    const float* W1     = (const float*)d_in[13];
    const float* b1     = (const float*)d_in[14];
    const float* W2     = (const float*)d_in[15];
    const float* b2     = (const float*)d_in[16];
    const float* g2     = (const float*)d_in[17];
    const float* be2    = (const float*)d_in[18];
    const float* Wfc    = (const float*)d_in[19];
    const float* bfc    = (const float*)d_in[20];
    float* out = (float*)d_out;

    float *x, *t0, *t1, *t2, *t3, *f1;
    cudaGetSymbolAddress((void**)&x,  g_x);
    cudaGetSymbolAddress((void**)&t0, g_t0);
    cudaGetSymbolAddress((void**)&t1, g_t1);
    cudaGetSymbolAddress((void**)&t2, g_t2);
    cudaGetSymbolAddress((void**)&t3, g_t3);
    cudaGetSymbolAddress((void**)&f1, g_f1);

    cudaFuncSetAttribute(attn_kernel,
                         cudaFuncAttributeMaxDynamicSharedMemorySize, ATTN_SMEM);

    embed_kernel<<<(MROWS * DM + 255) / 256, 256>>>(tokens, emb, pe, x);

    dim3 gDD(MROWS / BM, DM / BN);     // (16, 8)
    dim3 gDF(MROWS / BM, DFF / BN);    // (16, 32)
    dim3 gAttn(SEQ / 128, NH, BATCH);  // (4, 16, 4)

    for (int l = 0; l < NL; l++) {
        const float* wq = Wq + (size_t)l * DM * DM;
        const float* wk = Wk + (size_t)l * DM * DM;
        const float* wv = Wv + (size_t)l * DM * DM;
        const float* wo = Wo + (size_t)l * DM * DM;
        const float* w1 = W1 + (size_t)l * DM * DFF;
        const float* w2 = W2 + (size_t)l * DFF * DM;

        sgemm_bias<false><<<gDD, 256>>>(x, wq, bq + l * DM, t0, MROWS, DM, DM);
        sgemm_bias<false><<<gDD, 256>>>(x, wk, bk + l * DM, t1, MROWS, DM, DM);
        sgemm_bias<false><<<gDD, 256>>>(x, wv, bv + l * DM, t2, MROWS, DM, DM);

        attn_kernel<<<gAttn, 128, ATTN_SMEM>>>(t0, t1, t2, t3);

        sgemm_bias<false><<<gDD, 256>>>(t3, wo, bo + l * DM, t0, MROWS, DM, DM);
        ln_residual<<<MROWS, 256>>>(x, t0, g1 + l * DM, be1 + l * DM);

        sgemm_bias<true ><<<gDF, 256>>>(x,  w1, b1 + l * DFF, f1, MROWS, DFF, DM);
        sgemm_bias<false><<<gDD, 256>>>(f1, w2, b2 + l * DM,  t0, MROWS, DM, DFF);
        ln_residual<<<MROWS, 256>>>(x, t0, g2 + l * DM, be2 + l * DM);
    }

    dim3 gV(MROWS / BM, VOCAB / BN);   // (16, 250)
    sgemm_bias<false><<<gV, 256>>>(x, Wfc, bfc, out, MROWS, VOCAB, DM);
}

// round 5
// speedup vs baseline: 1.0479x; 1.0479x over previous
#include <cuda_runtime.h>
#include <cuda_bf16.h>
#include <math.h>
#include <stdint.h>

#define BATCH 4
#define SEQ   512
#define DM    1024
#define NH    16
#define NL    8
#define VOCAB 32000
#define HDIM  64
#define DFF   4096
#define MROWS (BATCH*SEQ)

__device__ float g_x [MROWS*DM];
__device__ float g_t0[MROWS*DM];
__device__ float g_t1[MROWS*DM];
__device__ float g_t2[MROWS*DM];
__device__ float g_t3[MROWS*DM];
__device__ float g_f1[MROWS*DFF];

__global__ void embed_kernel(const int* __restrict__ tokens,
                             const float* __restrict__ emb,
                             const float* __restrict__ pe,
                             float* __restrict__ x)
{
    int idx = blockIdx.x * blockDim.x + threadIdx.x;
    if (idx >= MROWS * DM) return;
    int d  = idx % DM;
    int nt = idx / DM;
    int n  = nt / SEQ;
    int tok = tokens[nt];
    x[idx] = emb[(size_t)tok * DM + d] + pe[(size_t)n * DM + d];
}

// ===================== tf32 mma.sync GEMM ===================================
// C(MxN) = A(MxK) @ B(KxN) + bias (opt ReLU).
// 128x128 tile, BK=32, 256 threads (8 warps, 4x2), warp tile 32x64.
// A in SMEM row-major [128][36] (pad), B transposed to n-major [128][36].
// Fragments via ldmatrix.m8n8.x4.b16 (b16 x4 pattern == tf32 m16n8k8 frags).

#define PADK 36

__device__ __forceinline__ uint32_t cvta_smem(const void* p){
    uint32_t a;
    asm("{ .reg .u64 t; cvta.to.shared.u64 t, %1; cvt.u32.u64 %0, t; }" : "=r"(a) : "l"(p));
    return a;
}
__device__ __forceinline__ float to_tf32(float x){
    uint32_t u;
    asm("cvt.rna.tf32.f32 %0, %1;" : "=r"(u) : "f"(x));
    return __uint_as_float(u);
}
__device__ __forceinline__ void ldm4(uint32_t* r, uint32_t addr){
    asm volatile("ldmatrix.sync.aligned.m8n8.x4.shared.b16 {%0,%1,%2,%3}, [%4];"
                 : "=r"(r[0]), "=r"(r[1]), "=r"(r[2]), "=r"(r[3]) : "r"(addr));
}
__device__ __forceinline__ void mma_tf32(float* c, const uint32_t* a, const uint32_t* b){
    asm volatile(
        "mma.sync.aligned.m16n8k8.row.col.f32.tf32.tf32.f32 "
        "{%0,%1,%2,%3}, {%4,%5,%6,%7}, {%8,%9}, {%0,%1,%2,%3};"
        : "+f"(c[0]), "+f"(c[1]), "+f"(c[2]), "+f"(c[3])
        : "r"(a[0]), "r"(a[1]), "r"(a[2]), "r"(a[3]), "r"(b[0]), "r"(b[1]));
}

template<bool RELU>
__global__ void __launch_bounds__(256, 1)
tf32_gemm(const float* __restrict__ A, const float* __restrict__ B,
          const float* __restrict__ bias, float* __restrict__ C,
          int Nn, int K)
{
    __shared__ float As[128 * PADK];
    __shared__ float Bs[128 * PADK];

    const int tid = threadIdx.x, lane = tid & 31, warp = tid >> 5;
    const int warp_m = warp & 3, warp_n = warp >> 2;
    const int mbase = blockIdx.x * 128, nbase = blockIdx.y * 128;

    const float* Ag = A + (size_t)mbase * K;
    const float* Bg = B + nbase;
    const int NC = K >> 5;

    // global-load mappings
    const int arow = tid >> 3, ak4 = tid & 7;          // A: row 0..31(+32p), col4 0..7
    const int r = tid & 3, q = tid >> 2;               // B quad mapping
    const int qi = q >> 5, qj = q & 31;

    // ldmatrix base addresses
    const int sel = lane >> 3, l7 = lane & 7;
    uint32_t as_base = cvta_smem(As), bs_base = cvta_smem(Bs);
    uint32_t a_addr[2], b_addr[4];
#pragma unroll
    for (int mt = 0; mt < 2; mt++){
        int row = warp_m * 32 + mt * 16 + (sel & 1) * 8 + l7;
        int col = (sel >> 1) * 4;
        a_addr[mt] = as_base + (row * PADK + col) * 4;
    }
#pragma unroll
    for (int np = 0; np < 4; np++){
        int nrow = warp_n * 64 + np * 16 + (sel >> 1) * 8 + l7;
        int col  = (sel & 1) * 4;
        b_addr[np] = bs_base + (nrow * PADK + col) * 4;
    }

    float acc[2][8][4];
#pragma unroll
    for (int mt = 0; mt < 2; mt++)
#pragma unroll
        for (int nt = 0; nt < 8; nt++)
#pragma unroll
            for (int i = 0; i < 4; i++) acc[mt][nt][i] = 0.f;

    float4 ra[2][4], rb[2][4];
#pragma unroll
    for (int p = 0; p < 4; p++)
        ra[0][p] = *(const float4*)(Ag + (size_t)(32*p + arow) * K + (ak4 << 2));
#pragma unroll
    for (int p = 0; p < 4; p++){
        int i = 2*p + qi;
        rb[0][p] = *(const float4*)(Bg + (size_t)(4*i + r) * Nn + 4*qj);
    }

    for (int c = 0; c < NC; c++){
        int cur = c & 1, nxt = cur ^ 1;

        if (c + 1 < NC){
            const float* Ac = Ag + (size_t)(c + 1) * 32;
#pragma unroll
            for (int p = 0; p < 4; p++)
                ra[nxt][p] = *(const float4*)(Ac + (size_t)(32*p + arow) * K + (ak4 << 2));
            const float* Bc = Bg + (size_t)(c + 1) * 32 * Nn;
#pragma unroll
            for (int p = 0; p < 4; p++){
                int i = 2*p + qi;
                rb[nxt][p] = *(const float4*)(Bc + (size_t)(4*i + r) * Nn + 4*qj);
            }
        }

        // A -> SMEM (rna tf32)
#pragma unroll
        for (int p = 0; p < 4; p++){
            float4 v = ra[cur][p];
            v.x = to_tf32(v.x); v.y = to_tf32(v.y);
            v.z = to_tf32(v.z); v.w = to_tf32(v.w);
            *(float4*)&As[(32*p + arow) * PADK + (ak4 << 2)] = v;
        }
        // B -> transpose in quad -> SMEM n-major (rna tf32)
#pragma unroll
        for (int p = 0; p < 4; p++){
            int i = 2*p + qi;
            float vv[4] = { rb[cur][p].x, rb[cur][p].y, rb[cur][p].z, rb[cur][p].w };
            float ww[4];
#pragma unroll
            for (int m = 0; m < 4; m++){
                int jj = (r + m) & 3;
                float s = vv[(r - m) & 3];
                ww[jj] = __shfl_sync(0xffffffffu, s, (lane & ~3) | jj);
            }
            float4 o4 = make_float4(to_tf32(ww[0]), to_tf32(ww[1]),
                                    to_tf32(ww[2]), to_tf32(ww[3]));
            int nn = 4*qj + r;
            *(float4*)&Bs[nn * PADK + 4*i] = o4;
        }
        __syncthreads();

        // compute: 4 ksteps of k8
#pragma unroll
        for (int ks = 0; ks < 4; ks++){
            uint32_t af[2][4], bf[4][4];
#pragma unroll
            for (int mt = 0; mt < 2; mt++) ldm4(af[mt], a_addr[mt] + ks * 32);
#pragma unroll
            for (int np = 0; np < 4; np++) ldm4(bf[np], b_addr[np] + ks * 32);
#pragma unroll
            for (int mt = 0; mt < 2; mt++)
#pragma unroll
                for (int np = 0; np < 4; np++){
                    mma_tf32(acc[mt][2*np + 0], af[mt], &bf[np][0]);
                    mma_tf32(acc[mt][2*np + 1], af[mt], &bf[np][2]);
                }
        }
        __syncthreads();
    }

    // epilogue: direct float2 stores with bias (+ReLU)
    const int g = lane >> 2, tig = lane & 3;
#pragma unroll
    for (int mt = 0; mt < 2; mt++){
        int row0 = mbase + warp_m * 32 + mt * 16 + g;
#pragma unroll
        for (int nt = 0; nt < 8; nt++){
            int col = nbase + warp_n * 64 + nt * 8 + 2 * tig;
            float b0 = bias[col], b1 = bias[col + 1];
            float2 v0 = make_float2(acc[mt][nt][0] + b0, acc[mt][nt][1] + b1);
            float2 v1 = make_float2(acc[mt][nt][2] + b0, acc[mt][nt][3] + b1);
            if (RELU){
                v0.x = fmaxf(v0.x, 0.f); v0.y = fmaxf(v0.y, 0.f);
                v1.x = fmaxf(v1.x, 0.f); v1.y = fmaxf(v1.y, 0.f);
            }
            *(float2*)&C[(size_t)row0 * Nn + col]       = v0;
            *(float2*)&C[(size_t)(row0 + 8) * Nn + col] = v1;
        }
    }
}

// ---------------- causal attention (flash-style, fp32) ----------------------
#define ATTN_SMEM ((128*65 + 64*65 + 64*65 + 128*65) * 4)

__global__ void __launch_bounds__(128)
attn_kernel(const float* __restrict__ q, const float* __restrict__ k,
            const float* __restrict__ v, float* __restrict__ o)
{
    extern __shared__ float sm[];
    float* qs  = sm;
    float* ks  = qs + 128 * 65;
    float* vs  = ks + 64 * 65;
    float* scs = vs + 64 * 65;

    int n  = blockIdx.z;
    int h  = blockIdx.y;
    int qt = blockIdx.x;
    int tid = threadIdx.x;
    int r = qt * 128 + tid;

    for (int i = tid; i < 128 * 16; i += 128) {
        int row = i >> 4, c4 = (i & 15) * 4;
        float4 t = *(const float4*)(q + ((size_t)(n * SEQ + qt * 128 + row)) * DM + h * HDIM + c4);
        qs[row * 65 + c4 + 0] = t.x; qs[row * 65 + c4 + 1] = t.y;
        qs[row * 65 + c4 + 2] = t.z; qs[row * 65 + c4 + 3] = t.w;
    }
    __syncthreads();

    float qreg[64];
#pragma unroll
    for (int d = 0; d < 64; d++) qreg[d] = qs[tid * 65 + d] * 0.125f;

    float m = -1e30f, l = 0.f;
    float acc[64];
#pragma unroll
    for (int d = 0; d < 64; d++) acc[d] = 0.f;

    int smax = qt * 128 + 127;
    for (int s0 = 0; s0 <= smax; s0 += 64) {
        for (int i = tid; i < 64 * 16; i += 128) {
            int row = i >> 4, c4 = (i & 15) * 4;
            size_t base = ((size_t)(n * SEQ + s0 + row)) * DM + h * HDIM + c4;
            float4 kk = *(const float4*)(k + base);
            ks[row * 65 + c4 + 0] = kk.x; ks[row * 65 + c4 + 1] = kk.y;
            ks[row * 65 + c4 + 2] = kk.z; ks[row * 65 + c4 + 3] = kk.w;
            float4 vv = *(const float4*)(v + base);
            vs[row * 65 + c4 + 0] = vv.x; vs[row * 65 + c4 + 1] = vv.y;
            vs[row * 65 + c4 + 2] = vv.z; vs[row * 65 + c4 + 3] = vv.w;
        }
        __syncthreads();

        float tmax = -1e30f;
        for (int s = 0; s < 64; s++) {
            float sc;
            if (s0 + s > r) {
                sc = -1e30f;
            } else {
                sc = 0.f;
#pragma unroll
                for (int d = 0; d < 64; d++) sc += qreg[d] * ks[s * 65 + d];
            }
            scs[tid * 65 + s] = sc;
            tmax = fmaxf(tmax, sc);
        }

        float nm = fmaxf(m, tmax);
        float cf = __expf(m - nm);
        l *= cf;
#pragma unroll
        for (int d = 0; d < 64; d++) acc[d] *= cf;

        for (int s = 0; s < 64; s++) {
            float p = __expf(scs[tid * 65 + s] - nm);
            l += p;
#pragma unroll
            for (int d = 0; d < 64; d++) acc[d] += p * vs[s * 65 + d];
        }
        m = nm;
        __syncthreads();
    }

    float inv = 1.f / l;
    float* op = o + ((size_t)(n * SEQ + r)) * DM + h * HDIM;
#pragma unroll
    for (int d0 = 0; d0 < 64; d0 += 4) {
        float4 t;
        t.x = acc[d0 + 0] * inv; t.y = acc[d0 + 1] * inv;
        t.z = acc[d0 + 2] * inv; t.w = acc[d0 + 3] * inv;
        *(float4*)(op + d0) = t;
    }
}

// ---------------- residual + LayerNorm: x += LN(o)*g + b --------------------
__global__ void __launch_bounds__(256)
ln_residual(float* __restrict__ x, const float* __restrict__ o,
            const float* __restrict__ g, const float* __restrict__ b)
{
    __shared__ float red[256];
    __shared__ float s_mean, s_rstd;
    int row = blockIdx.x;
    int tid = threadIdx.x;
    const float* orow = o + (size_t)row * DM;
    float*       xrow = x + (size_t)row * DM;

    float s = 0.f;
    for (int d = tid; d < DM; d += 256) s += orow[d];
    red[tid] = s; __syncthreads();
    for (int off = 128; off > 0; off >>= 1) {
        if (tid < off) red[tid] += red[tid + off];
        __syncthreads();
    }
    if (tid == 0) s_mean = red[0] * (1.f / DM);
    __syncthreads();
    float mean = s_mean;

    float vv = 0.f;
    for (int d = tid; d < DM; d += 256) { float t = orow[d] - mean; vv += t * t; }
    red[tid] = vv; __syncthreads();
    for (int off = 128; off > 0; off >>= 1) {
        if (tid < off) red[tid] += red[tid + off];
        __syncthreads();
    }
    if (tid == 0) s_rstd = rsqrtf(red[0] * (1.f / DM) + 1e-5f);
    __syncthreads();
    float rstd = s_rstd;

    for (int d = tid; d < DM; d += 256)
        xrow[d] += (orow[d] - mean) * rstd * g[d] + b[d];
}

// ---------------- launch ----------------------------------------------------
extern "C" void kernel_launch(void* const* d_in, const int* in_sizes, int n_in,
                              void* d_out, int out_size)
{
    const int*   tokens = (const int*)  d_in[0];
    const float* emb    = (const float*)d_in[1];
    const float* pe     = (const float*)d_in[2];
    const float* Wq     = (const float*)d_in[3];
    const float* bq     = (const float*)d_in[4];
    const float* Wk     = (const float*)d_in[5];
    const float* bk     = (const float*)d_in[6];
    const float* Wv     = (const float*)d_in[7];
    const float* bv     = (const float*)d_in[8];
    const float* Wo     = (const float*)d_in[9];
    const float* bo     = (const float*)d_in[10];
    const float* g1     = (const float*)d_in[11];
    const float* be1    = (const float*)d_in[12];
    const float* W1     = (const float*)d_in[13];
    const float* b1     = (const float*)d_in[14];
    const float* W2     = (const float*)d_in[15];
    const float* b2     = (const float*)d_in[16];
    const float* g2     = (const float*)d_in[17];
    const float* be2    = (const float*)d_in[18];
    const float* Wfc    = (const float*)d_in[19];
    const float* bfc    = (const float*)d_in[20];
    float* out = (float*)d_out;

    float *x, *t0, *t1, *t2, *t3, *f1;
    cudaGetSymbolAddress((void**)&x,  g_x);
    cudaGetSymbolAddress((void**)&t0, g_t0);
    cudaGetSymbolAddress((void**)&t1, g_t1);
    cudaGetSymbolAddress((void**)&t2, g_t2);
    cudaGetSymbolAddress((void**)&t3, g_t3);
    cudaGetSymbolAddress((void**)&f1, g_f1);

    cudaFuncSetAttribute(attn_kernel,
                         cudaFuncAttributeMaxDynamicSharedMemorySize, ATTN_SMEM);

    embed_kernel<<<(MROWS * DM + 255) / 256, 256>>>(tokens, emb, pe, x);

    dim3 gDD(MROWS / 128, DM / 128);
    dim3 gDF(MROWS / 128, DFF / 128);
    dim3 gAttn(SEQ / 128, NH, BATCH);

    for (int l = 0; l < NL; l++) {
        const float* wq = Wq + (size_t)l * DM * DM;
        const float* wk = Wk + (size_t)l * DM * DM;
        const float* wv = Wv + (size_t)l * DM * DM;
        const float* wo = Wo + (size_t)l * DM * DM;
        const float* w1 = W1 + (size_t)l * DM * DFF;
        const float* w2 = W2 + (size_t)l * DFF * DM;

        tf32_gemm<false><<<gDD, 256>>>(x, wq, bq + l * DM, t0, DM, DM);
        tf32_gemm<false><<<gDD, 256>>>(x, wk, bk + l * DM, t1, DM, DM);
        tf32_gemm<false><<<gDD, 256>>>(x, wv, bv + l * DM, t2, DM, DM);

        attn_kernel<<<gAttn, 128, ATTN_SMEM>>>(t0, t1, t2, t3);

        tf32_gemm<false><<<gDD, 256>>>(t3, wo, bo + l * DM, t0, DM, DM);
        ln_residual<<<MROWS, 256>>>(x, t0, g1 + l * DM, be1 + l * DM);

        tf32_gemm<true ><<<gDF, 256>>>(x,  w1, b1 + l * DFF, f1, DFF, DM);
        tf32_gemm<false><<<gDD, 256>>>(f1, w2, b2 + l * DM,  t0, DM, DFF);
        ln_residual<<<MROWS, 256>>>(x, t0, g2 + l * DM, be2 + l * DM);
    }

    dim3 gV(MROWS / 128, VOCAB / 128);
    tf32_gemm<false><<<gV, 256>>>(x, Wfc, bfc, out, VOCAB, DM);
}

// round 6
// speedup vs baseline: 2.8902x; 2.7581x over previous
#include <cuda_runtime.h>
#include <cuda_bf16.h>
#include <math.h>
#include <stdint.h>

#define BATCH 4
#define SEQ   512
#define DM    1024
#define NH    16
#define NL    8
#define VOCAB 32000
#define HDIM  64
#define DFF   4096
#define MROWS (BATCH*SEQ)

__device__ float g_x [MROWS*DM];
__device__ float g_t0[MROWS*DM];
__device__ float g_t1[MROWS*DM];
__device__ float g_t2[MROWS*DM];
__device__ float g_t3[MROWS*DM];
__device__ float g_f1[MROWS*DFF];

__global__ void embed_kernel(const int* __restrict__ tokens,
                             const float* __restrict__ emb,
                             const float* __restrict__ pe,
                             float* __restrict__ x)
{
    int idx = blockIdx.x * blockDim.x + threadIdx.x;
    if (idx >= MROWS * DM) return;
    int d  = idx % DM;
    int nt = idx / DM;
    int n  = nt / SEQ;
    int tok = tokens[nt];
    x[idx] = emb[(size_t)tok * DM + d] + pe[(size_t)n * DM + d];
}

// ===================== tf32 mma.sync GEMM (pipelined) ========================
// C(MxN)=A(MxK)@B(KxN)+bias (opt ReLU). Tile 128x64, BK=32, 2-stage smem ring.
// 256 thr (8 warps 4x2), warp tile 32x32. A row-major smem [128][36] (ldmatrix),
// B k-major smem [32][72] (direct LDS fragments, no transpose).
#define PADA 36
#define PADB 72
#define A_FL (128*PADA)          // 4608 floats
#define B_FL (32*PADB)           // 2304 floats
#define STG_FL (A_FL + B_FL)     // 6912 floats
#define STG_BYTES (STG_FL*4)     // 27648
#define GEMM_SMEM (2*STG_BYTES)  // 55296

__device__ __forceinline__ uint32_t cvta_smem(const void* p){
    uint32_t a;
    asm("{ .reg .u64 t; cvta.to.shared.u64 t, %1; cvt.u32.u64 %0, t; }" : "=r"(a) : "l"(p));
    return a;
}
__device__ __forceinline__ float to_tf32(float x){
    uint32_t u;
    asm("cvt.rna.tf32.f32 %0, %1;" : "=r"(u) : "f"(x));
    return __uint_as_float(u);
}
__device__ __forceinline__ void ldm4(uint32_t* r, uint32_t addr){
    asm volatile("ldmatrix.sync.aligned.m8n8.x4.shared.b16 {%0,%1,%2,%3}, [%4];"
                 : "=r"(r[0]), "=r"(r[1]), "=r"(r[2]), "=r"(r[3]) : "r"(addr));
}
__device__ __forceinline__ void mma_tf32(float* c, const uint32_t* a, const uint32_t* b){
    asm volatile(
        "mma.sync.aligned.m16n8k8.row.col.f32.tf32.tf32.f32 "
        "{%0,%1,%2,%3}, {%4,%5,%6,%7}, {%8,%9}, {%0,%1,%2,%3};"
        : "+f"(c[0]), "+f"(c[1]), "+f"(c[2]), "+f"(c[3])
        : "r"(a[0]), "r"(a[1]), "r"(a[2]), "r"(a[3]), "r"(b[0]), "r"(b[1]));
}

template<bool RELU>
__global__ void __launch_bounds__(256, 2)
tf32_gemm(const float* __restrict__ A, const float* __restrict__ B,
          const float* __restrict__ bias, float* __restrict__ C,
          int Nn, int K)
{
    extern __shared__ float smem[];
    const int tid = threadIdx.x, lane = tid & 31, warp = tid >> 5;
    const int warp_m = warp & 3, warp_n = warp >> 2;
    const int mbase = blockIdx.x * 128, nbase = blockIdx.y * 64;

    const float* Ag = A + (size_t)mbase * K;
    const float* Bg = B + nbase;
    const int NC = K >> 5;

    // global load mappings
    const int arow = tid >> 3, ak4 = (tid & 7) << 2;   // A: 4 rows (32 apart), 4 floats
    const int brow = tid >> 4, bcol = (tid & 15) << 2; // B: 2 rows (16 apart), 4 floats

    // fragment mappings
    const int g = lane >> 2, tig = lane & 3;
    const int sel = lane >> 3, l7 = lane & 7;
    const uint32_t smem_u = cvta_smem(smem);
    uint32_t a_rel[2];
#pragma unroll
    for (int mt = 0; mt < 2; mt++){
        int row = warp_m * 32 + mt * 16 + (sel & 1) * 8 + l7;
        int col = (sel >> 1) * 4;
        a_rel[mt] = (uint32_t)(row * PADA + col) * 4u;
    }
    const int bidx = tig * PADB + warp_n * 32 + g;   // float index into B stage

    float acc[2][4][4];
#pragma unroll
    for (int mt = 0; mt < 2; mt++)
#pragma unroll
        for (int np = 0; np < 4; np++)
#pragma unroll
            for (int i = 0; i < 4; i++) acc[mt][np][i] = 0.f;

    float4 ra[4]; float4 rb[2];
    // prologue: LDG chunk 0 + STS stage 0
#pragma unroll
    for (int p = 0; p < 4; p++)
        ra[p] = *(const float4*)(Ag + (size_t)(32*p + arow) * K + ak4);
#pragma unroll
    for (int p = 0; p < 2; p++)
        rb[p] = *(const float4*)(Bg + (size_t)(16*p + brow) * Nn + bcol);
    {
        float* As_ = smem; float* Bs_ = smem + A_FL;
#pragma unroll
        for (int p = 0; p < 4; p++){
            float4 v = ra[p];
            v.x = to_tf32(v.x); v.y = to_tf32(v.y); v.z = to_tf32(v.z); v.w = to_tf32(v.w);
            *(float4*)&As_[(32*p + arow) * PADA + ak4] = v;
        }
#pragma unroll
        for (int p = 0; p < 2; p++){
            float4 v = rb[p];
            v.x = to_tf32(v.x); v.y = to_tf32(v.y); v.z = to_tf32(v.z); v.w = to_tf32(v.w);
            *(float4*)&Bs_[(16*p + brow) * PADB + bcol] = v;
        }
    }

    for (int c = 0; c < NC; c++){
        const int s = c & 1;
        __syncthreads();

        if (c + 1 < NC){
            const float* Ac = Ag + (size_t)(c + 1) * 32;
#pragma unroll
            for (int p = 0; p < 4; p++)
                ra[p] = *(const float4*)(Ac + (size_t)(32*p + arow) * K + ak4);
            const float* Bc = Bg + (size_t)(c + 1) * 32 * Nn;
#pragma unroll
            for (int p = 0; p < 2; p++)
                rb[p] = *(const float4*)(Bc + (size_t)(16*p + brow) * Nn + bcol);
        }

        // compute chunk c from stage s (frag loads pipelined over ksteps)
        const uint32_t abase = smem_u + (uint32_t)s * STG_BYTES;
        const float* Bst = smem + s * STG_FL + A_FL;

        uint32_t af[2][8];
        uint32_t bf[2][4][2];
        ldm4(&af[0][0], abase + a_rel[0]);
        ldm4(&af[0][4], abase + a_rel[1]);
#pragma unroll
        for (int np = 0; np < 4; np++){
            bf[0][np][0] = __float_as_uint(Bst[bidx + np*8]);
            bf[0][np][1] = __float_as_uint(Bst[bidx + np*8 + 4*PADB]);
        }
#pragma unroll
        for (int ks = 0; ks < 4; ks++){
            const int b = ks & 1, nb = b ^ 1;
            if (ks < 3){
                ldm4(&af[nb][0], abase + a_rel[0] + (ks+1)*32);
                ldm4(&af[nb][4], abase + a_rel[1] + (ks+1)*32);
                const float* Bk = Bst + (ks+1)*8*PADB;
#pragma unroll
                for (int np = 0; np < 4; np++){
                    bf[nb][np][0] = __float_as_uint(Bk[bidx + np*8]);
                    bf[nb][np][1] = __float_as_uint(Bk[bidx + np*8 + 4*PADB]);
                }
            }
#pragma unroll
            for (int mt = 0; mt < 2; mt++)
#pragma unroll
                for (int np = 0; np < 4; np++)
                    mma_tf32(acc[mt][np], &af[b][4*mt], bf[b][np]);
        }

        // store chunk c+1 into other stage (safe: all warps passed top sync)
        if (c + 1 < NC){
            float* As_ = smem + (s ^ 1) * STG_FL;
            float* Bs_ = As_ + A_FL;
#pragma unroll
            for (int p = 0; p < 4; p++){
                float4 v = ra[p];
                v.x = to_tf32(v.x); v.y = to_tf32(v.y); v.z = to_tf32(v.z); v.w = to_tf32(v.w);
                *(float4*)&As_[(32*p + arow) * PADA + ak4] = v;
            }
#pragma unroll
            for (int p = 0; p < 2; p++){
                float4 v = rb[p];
                v.x = to_tf32(v.x); v.y = to_tf32(v.y); v.z = to_tf32(v.z); v.w = to_tf32(v.w);
                *(float4*)&Bs_[(16*p + brow) * PADB + bcol] = v;
            }
        }
    }

    // epilogue: direct float2 stores with bias (+ReLU)
#pragma unroll
    for (int mt = 0; mt < 2; mt++){
        int row0 = mbase + warp_m * 32 + mt * 16 + g;
#pragma unroll
        for (int np = 0; np < 4; np++){
            int col = nbase + warp_n * 32 + np * 8 + 2 * tig;
            float b0 = bias[col], b1 = bias[col + 1];
            float2 v0 = make_float2(acc[mt][np][0] + b0, acc[mt][np][1] + b1);
            float2 v1 = make_float2(acc[mt][np][2] + b0, acc[mt][np][3] + b1);
            if (RELU){
                v0.x = fmaxf(v0.x, 0.f); v0.y = fmaxf(v0.y, 0.f);
                v1.x = fmaxf(v1.x, 0.f); v1.y = fmaxf(v1.y, 0.f);
            }
            *(float2*)&C[(size_t)row0 * Nn + col]       = v0;
            *(float2*)&C[(size_t)(row0 + 8) * Nn + col] = v1;
        }
    }
}

// ---------------- causal attention (flash-style, fp32) ----------------------
#define ATTN_SMEM ((128*65 + 64*65 + 64*65 + 128*65) * 4)

__global__ void __launch_bounds__(128)
attn_kernel(const float* __restrict__ q, const float* __restrict__ k,
            const float* __restrict__ v, float* __restrict__ o)
{
    extern __shared__ float sm[];
    float* qs  = sm;
    float* ks  = qs + 128 * 65;
    float* vs  = ks + 64 * 65;
    float* scs = vs + 64 * 65;

    int n  = blockIdx.z;
    int h  = blockIdx.y;
    int qt = blockIdx.x;
    int tid = threadIdx.x;
    int r = qt * 128 + tid;

    for (int i = tid; i < 128 * 16; i += 128) {
        int row = i >> 4, c4 = (i & 15) * 4;
        float4 t = *(const float4*)(q + ((size_t)(n * SEQ + qt * 128 + row)) * DM + h * HDIM + c4);
        qs[row * 65 + c4 + 0] = t.x; qs[row * 65 + c4 + 1] = t.y;
        qs[row * 65 + c4 + 2] = t.z; qs[row * 65 + c4 + 3] = t.w;
    }
    __syncthreads();

    float qreg[64];
#pragma unroll
    for (int d = 0; d < 64; d++) qreg[d] = qs[tid * 65 + d] * 0.125f;

    float m = -1e30f, l = 0.f;
    float acc[64];
#pragma unroll
    for (int d = 0; d < 64; d++) acc[d] = 0.f;

    int smax = qt * 128 + 127;
    for (int s0 = 0; s0 <= smax; s0 += 64) {
        for (int i = tid; i < 64 * 16; i += 128) {
            int row = i >> 4, c4 = (i & 15) * 4;
            size_t base = ((size_t)(n * SEQ + s0 + row)) * DM + h * HDIM + c4;
            float4 kk = *(const float4*)(k + base);
            ks[row * 65 + c4 + 0] = kk.x; ks[row * 65 + c4 + 1] = kk.y;
            ks[row * 65 + c4 + 2] = kk.z; ks[row * 65 + c4 + 3] = kk.w;
            float4 vv = *(const float4*)(v + base);
            vs[row * 65 + c4 + 0] = vv.x; vs[row * 65 + c4 + 1] = vv.y;
            vs[row * 65 + c4 + 2] = vv.z; vs[row * 65 + c4 + 3] = vv.w;
        }
        __syncthreads();

        float tmax = -1e30f;
        for (int s = 0; s < 64; s++) {
            float sc;
            if (s0 + s > r) {
                sc = -1e30f;
            } else {
                sc = 0.f;
#pragma unroll
                for (int d = 0; d < 64; d++) sc += qreg[d] * ks[s * 65 + d];
            }
            scs[tid * 65 + s] = sc;
            tmax = fmaxf(tmax, sc);
        }

        float nm = fmaxf(m, tmax);
        float cf = __expf(m - nm);
        l *= cf;
#pragma unroll
        for (int d = 0; d < 64; d++) acc[d] *= cf;

        for (int s = 0; s < 64; s++) {
            float p = __expf(scs[tid * 65 + s] - nm);
            l += p;
#pragma unroll
            for (int d = 0; d < 64; d++) acc[d] += p * vs[s * 65 + d];
        }
        m = nm;
        __syncthreads();
    }

    float inv = 1.f / l;
    float* op = o + ((size_t)(n * SEQ + r)) * DM + h * HDIM;
#pragma unroll
    for (int d0 = 0; d0 < 64; d0 += 4) {
        float4 t;
        t.x = acc[d0 + 0] * inv; t.y = acc[d0 + 1] * inv;
        t.z = acc[d0 + 2] * inv; t.w = acc[d0 + 3] * inv;
        *(float4*)(op + d0) = t;
    }
}

// ---------------- residual + LayerNorm: x += LN(o)*g + b --------------------
__global__ void __launch_bounds__(256)
ln_residual(float* __restrict__ x, const float* __restrict__ o,
            const float* __restrict__ g, const float* __restrict__ b)
{
    __shared__ float red[256];
    __shared__ float s_mean, s_rstd;
    int row = blockIdx.x;
    int tid = threadIdx.x;
    const float* orow = o + (size_t)row * DM;
    float*       xrow = x + (size_t)row * DM;

    float s = 0.f;
    for (int d = tid; d < DM; d += 256) s += orow[d];
    red[tid] = s; __syncthreads();
    for (int off = 128; off > 0; off >>= 1) {
        if (tid < off) red[tid] += red[tid + off];
        __syncthreads();
    }
    if (tid == 0) s_mean = red[0] * (1.f / DM);
    __syncthreads();
    float mean = s_mean;

    float vv = 0.f;
    for (int d = tid; d < DM; d += 256) { float t = orow[d] - mean; vv += t * t; }
    red[tid] = vv; __syncthreads();
    for (int off = 128; off > 0; off >>= 1) {
        if (tid < off) red[tid] += red[tid + off];
        __syncthreads();
    }
    if (tid == 0) s_rstd = rsqrtf(red[0] * (1.f / DM) + 1e-5f);
    __syncthreads();
    float rstd = s_rstd;

    for (int d = tid; d < DM; d += 256)
        xrow[d] += (orow[d] - mean) * rstd * g[d] + b[d];
}

// ---------------- launch ----------------------------------------------------
extern "C" void kernel_launch(void* const* d_in, const int* in_sizes, int n_in,
                              void* d_out, int out_size)
{
    const int*   tokens = (const int*)  d_in[0];
    const float* emb    = (const float*)d_in[1];
    const float* pe     = (const float*)d_in[2];
    const float* Wq     = (const float*)d_in[3];
    const float* bq     = (const float*)d_in[4];
    const float* Wk     = (const float*)d_in[5];
    const float* bk     = (const float*)d_in[6];
    const float* Wv     = (const float*)d_in[7];
    const float* bv     = (const float*)d_in[8];
    const float* Wo     = (const float*)d_in[9];
    const float* bo     = (const float*)d_in[10];
    const float* g1     = (const float*)d_in[11];
    const float* be1    = (const float*)d_in[12];
    const float* W1     = (const float*)d_in[13];
    const float* b1     = (const float*)d_in[14];
    const float* W2     = (const float*)d_in[15];
    const float* b2     = (const float*)d_in[16];
    const float* g2     = (const float*)d_in[17];
    const float* be2    = (const float*)d_in[18];
    const float* Wfc    = (const float*)d_in[19];
    const float* bfc    = (const float*)d_in[20];
    float* out = (float*)d_out;

    float *x, *t0, *t1, *t2, *t3, *f1;
    cudaGetSymbolAddress((void**)&x,  g_x);
    cudaGetSymbolAddress((void**)&t0, g_t0);
    cudaGetSymbolAddress((void**)&t1, g_t1);
    cudaGetSymbolAddress((void**)&t2, g_t2);
    cudaGetSymbolAddress((void**)&t3, g_t3);
    cudaGetSymbolAddress((void**)&f1, g_f1);

    cudaFuncSetAttribute(attn_kernel,
                         cudaFuncAttributeMaxDynamicSharedMemorySize, ATTN_SMEM);
    cudaFuncSetAttribute(tf32_gemm<false>,
                         cudaFuncAttributeMaxDynamicSharedMemorySize, GEMM_SMEM);
    cudaFuncSetAttribute(tf32_gemm<true>,
                         cudaFuncAttributeMaxDynamicSharedMemorySize, GEMM_SMEM);

    embed_kernel<<<(MROWS * DM + 255) / 256, 256>>>(tokens, emb, pe, x);

    dim3 gDD(MROWS / 128, DM / 64);     // (16, 16)
    dim3 gDF(MROWS / 128, DFF / 64);    // (16, 64)
    dim3 gAttn(SEQ / 128, NH, BATCH);

    for (int l = 0; l < NL; l++) {
        const float* wq = Wq + (size_t)l * DM * DM;
        const float* wk = Wk + (size_t)l * DM * DM;
        const float* wv = Wv + (size_t)l * DM * DM;
        const float* wo = Wo + (size_t)l * DM * DM;
        const float* w1 = W1 + (size_t)l * DM * DFF;
        const float* w2 = W2 + (size_t)l * DFF * DM;

        tf32_gemm<false><<<gDD, 256, GEMM_SMEM>>>(x, wq, bq + l * DM, t0, DM, DM);
        tf32_gemm<false><<<gDD, 256, GEMM_SMEM>>>(x, wk, bk + l * DM, t1, DM, DM);
        tf32_gemm<false><<<gDD, 256, GEMM_SMEM>>>(x, wv, bv + l * DM, t2, DM, DM);

        attn_kernel<<<gAttn, 128, ATTN_SMEM>>>(t0, t1, t2, t3);

        tf32_gemm<false><<<gDD, 256, GEMM_SMEM>>>(t3, wo, bo + l * DM, t0, DM, DM);
        ln_residual<<<MROWS, 256>>>(x, t0, g1 + l * DM, be1 + l * DM);

        tf32_gemm<true ><<<gDF, 256, GEMM_SMEM>>>(x,  w1, b1 + l * DFF, f1, DFF, DM);
        tf32_gemm<false><<<gDD, 256, GEMM_SMEM>>>(f1, w2, b2 + l * DM,  t0, DM, DFF);
        ln_residual<<<MROWS, 256>>>(x, t0, g2 + l * DM, be2 + l * DM);
    }

    dim3 gV(MROWS / 128, VOCAB / 64);   // (16, 500)
    tf32_gemm<false><<<gV, 256, GEMM_SMEM>>>(x, Wfc, bfc, out, VOCAB, DM);
}